// round 1
// baseline (speedup 1.0000x reference)
#include <cuda_runtime.h>

// Problem constants
#define B_   8
#define C_   256
#define N_   4096
#define CQ_  32

// ---------------------------------------------------------------------------
// Scratch (device globals: allocation-free per harness rules)
// q, k stored [b][32][N]; v stored [b][256][N]  (all K-major along N)
// ---------------------------------------------------------------------------
__device__ float g_q[B_ * CQ_ * N_];
__device__ float g_k[B_ * CQ_ * N_];
__device__ float g_v[B_ * C_  * N_];

// ---------------------------------------------------------------------------
// Projection kernel for q and k (M = 32 each). Block tile: 32 x 128, K=256.
// grid = (N/128, 2(q|k), B), 256 threads. Thread tile 2(o) x 8(n).
// ---------------------------------------------------------------------------
__global__ __launch_bounds__(256, 2)
void proj_qk_kernel(const float* __restrict__ x,
                    const float* __restrict__ wq, const float* __restrict__ bq,
                    const float* __restrict__ wk, const float* __restrict__ bk)
{
    const int b     = blockIdx.z;
    const int which = blockIdx.y;           // 0 -> q, 1 -> k
    const int n0    = blockIdx.x * 128;

    const float* W    = which ? wk : wq;
    const float* bias = which ? bk : bq;
    float*       out  = which ? g_k : g_q;

    __shared__ float Wt[16][36];     // [k][o], transposed W chunk
    __shared__ float Xs[16][132];    // [k][n]

    const int tid = threadIdx.x;
    const int to  = tid >> 4;        // 16 o-groups -> o = to*2
    const int tn  = tid & 15;        // 16 n-groups -> n = tn*8

    float acc[2][8];
#pragma unroll
    for (int r = 0; r < 2; r++)
#pragma unroll
        for (int c = 0; c < 8; c++) acc[r][c] = 0.f;

    for (int kk = 0; kk < 256; kk += 16) {
        // W chunk: 32 o x 16 k = 512 elems -> 2/thread
        {
            int e = tid * 2;
            int o = e >> 4;
            int k = e & 15;
            float2 wv2 = *(const float2*)&W[o * 256 + kk + k];
            Wt[k][o]     = wv2.x;
            Wt[k + 1][o] = wv2.y;
        }
        // X chunk: 16 k x 128 n -> 8/thread (2 float4), coalesced
        {
            int k = tid >> 4;
            int n = (tid & 15) * 8;
            const float* xp = &x[((size_t)b * C_ + (kk + k)) * N_ + n0 + n];
            *(float4*)&Xs[k][n]     = *(const float4*)xp;
            *(float4*)&Xs[k][n + 4] = *(const float4*)(xp + 4);
        }
        __syncthreads();
#pragma unroll
        for (int k = 0; k < 16; k++) {
            float a0 = Wt[k][to * 2 + 0];
            float a1 = Wt[k][to * 2 + 1];
            float4 b0 = *(float4*)&Xs[k][tn * 8];
            float4 b1 = *(float4*)&Xs[k][tn * 8 + 4];
            float rb[8] = {b0.x, b0.y, b0.z, b0.w, b1.x, b1.y, b1.z, b1.w};
#pragma unroll
            for (int c = 0; c < 8; c++) {
                acc[0][c] += a0 * rb[c];
                acc[1][c] += a1 * rb[c];
            }
        }
        __syncthreads();
    }
#pragma unroll
    for (int r = 0; r < 2; r++) {
        int o = to * 2 + r;
        float bv_ = bias[o];
        float* op = &out[((size_t)b * CQ_ + o) * N_ + n0 + tn * 8];
        float4 o0 = {acc[r][0] + bv_, acc[r][1] + bv_, acc[r][2] + bv_, acc[r][3] + bv_};
        float4 o1 = {acc[r][4] + bv_, acc[r][5] + bv_, acc[r][6] + bv_, acc[r][7] + bv_};
        *(float4*)op       = o0;
        *(float4*)(op + 4) = o1;
    }
}

// ---------------------------------------------------------------------------
// Projection kernel for v (M = 256). Block tile 128 x 128, K=256.
// grid = (N/128, 2, B), 256 threads. Thread tile 8 x 8.
// ---------------------------------------------------------------------------
__global__ __launch_bounds__(256, 2)
void proj_v_kernel(const float* __restrict__ x,
                   const float* __restrict__ wv, const float* __restrict__ bv)
{
    const int b  = blockIdx.z;
    const int o0g = blockIdx.y * 128;
    const int n0 = blockIdx.x * 128;

    __shared__ float Wt[16][132];    // [k][o]
    __shared__ float Xs[16][132];    // [k][n]

    const int tid = threadIdx.x;
    const int to  = tid >> 4;        // o = to*8
    const int tn  = tid & 15;        // n = tn*8

    float acc[8][8];
#pragma unroll
    for (int r = 0; r < 8; r++)
#pragma unroll
        for (int c = 0; c < 8; c++) acc[r][c] = 0.f;

    for (int kk = 0; kk < 256; kk += 16) {
        // W chunk: 128 o x 16 k = 2048 elems -> 8/thread
        {
            int o = tid >> 1;                 // 0..127
            int k = (tid & 1) * 8;            // 0 or 8
            const float* wp = &wv[(size_t)(o0g + o) * 256 + kk + k];
            float4 w0 = *(const float4*)wp;
            float4 w1 = *(const float4*)(wp + 4);
            Wt[k + 0][o] = w0.x; Wt[k + 1][o] = w0.y;
            Wt[k + 2][o] = w0.z; Wt[k + 3][o] = w0.w;
            Wt[k + 4][o] = w1.x; Wt[k + 5][o] = w1.y;
            Wt[k + 6][o] = w1.z; Wt[k + 7][o] = w1.w;
        }
        // X chunk: 16 k x 128 n -> 8/thread
        {
            int k = tid >> 4;
            int n = (tid & 15) * 8;
            const float* xp = &x[((size_t)b * C_ + (kk + k)) * N_ + n0 + n];
            *(float4*)&Xs[k][n]     = *(const float4*)xp;
            *(float4*)&Xs[k][n + 4] = *(const float4*)(xp + 4);
        }
        __syncthreads();
#pragma unroll
        for (int k = 0; k < 16; k++) {
            float4 a0 = *(float4*)&Wt[k][to * 8];
            float4 a1 = *(float4*)&Wt[k][to * 8 + 4];
            float4 b0 = *(float4*)&Xs[k][tn * 8];
            float4 b1 = *(float4*)&Xs[k][tn * 8 + 4];
            float ra[8] = {a0.x, a0.y, a0.z, a0.w, a1.x, a1.y, a1.z, a1.w};
            float rb[8] = {b0.x, b0.y, b0.z, b0.w, b1.x, b1.y, b1.z, b1.w};
#pragma unroll
            for (int r = 0; r < 8; r++)
#pragma unroll
                for (int c = 0; c < 8; c++) acc[r][c] += ra[r] * rb[c];
        }
        __syncthreads();
    }
#pragma unroll
    for (int r = 0; r < 8; r++) {
        int o = o0g + to * 8 + r;
        float bb = bv[o];
        float* op = &g_v[((size_t)b * C_ + o) * N_ + n0 + tn * 8];
        float4 o0 = {acc[r][0] + bb, acc[r][1] + bb, acc[r][2] + bb, acc[r][3] + bb};
        float4 o1 = {acc[r][4] + bb, acc[r][5] + bb, acc[r][6] + bb, acc[r][7] + bb};
        *(float4*)op       = o0;
        *(float4*)(op + 4) = o1;
    }
}

// ---------------------------------------------------------------------------
// Fused flash attention + epilogue.
// grid = (N/64, B), 256 threads, 2 blocks/SM.
// Per block: 64 query rows (i), stream 64-key tiles (j), online softmax,
// acc[64 x 256] fp32 in registers (8x8 per thread), epilogue y = g*out + x.
// ---------------------------------------------------------------------------
#define QS_STRIDE 33
#define SS_STRIDE 65
#define VT_STRIDE 260
#define O2_STRIDE 257

#define QS_OFF 0
#define KS_OFF (QS_OFF + 64 * QS_STRIDE)
#define SS_OFF (KS_OFF + 64 * QS_STRIDE)
#define VT_OFF (SS_OFF + 64 * SS_STRIDE)
#define M_OFF  (VT_OFF + 64 * VT_STRIDE)
#define L_OFF  (M_OFF + 64)
#define CS_OFF (L_OFF + 64)
#define SMEM_FLOATS (CS_OFF + 64)
#define SMEM_BYTES  (SMEM_FLOATS * 4)

__global__ __launch_bounds__(256, 2)
void attn_kernel(const float* __restrict__ x,
                 const float* __restrict__ gamma,
                 float* __restrict__ y)
{
    extern __shared__ float sm[];
    float* qs = sm + QS_OFF;   // [i][33]  (i-major, o fast)
    float* ks = sm + KS_OFF;   // [j][33]
    float* Ss = sm + SS_OFF;   // [i][65]  scores -> probabilities
    float* vt = sm + VT_OFF;   // [j][260] transposed v tile; reused as outs2
    float* m_ = sm + M_OFF;
    float* l_ = sm + L_OFF;
    float* cs = sm + CS_OFF;

    const int b   = blockIdx.y;
    const int i0g = blockIdx.x * 64;
    const int tid = threadIdx.x;

    // --- load q tile: q[b][o][i0g + i] -> qs[i][o]  (32 x 64, transposed) ---
    {
        int e  = tid * 2;
        int o  = e >> 4;            // 0..31
        int i4 = e & 15;            // even float4 index along i
        const float* qp = &g_q[((size_t)b * CQ_ + o) * N_ + i0g + i4 * 4];
        float4 a = *(const float4*)qp;
        float4 c = *(const float4*)(qp + 4);
        qs[(i4 * 4 + 0) * QS_STRIDE + o] = a.x;
        qs[(i4 * 4 + 1) * QS_STRIDE + o] = a.y;
        qs[(i4 * 4 + 2) * QS_STRIDE + o] = a.z;
        qs[(i4 * 4 + 3) * QS_STRIDE + o] = a.w;
        qs[(i4 * 4 + 4) * QS_STRIDE + o] = c.x;
        qs[(i4 * 4 + 5) * QS_STRIDE + o] = c.y;
        qs[(i4 * 4 + 6) * QS_STRIDE + o] = c.z;
        qs[(i4 * 4 + 7) * QS_STRIDE + o] = c.w;
    }
    if (tid < 64) { m_[tid] = -1e30f; l_[tid] = 0.f; }

    float acc[8][8];
#pragma unroll
    for (int r = 0; r < 8; r++)
#pragma unroll
        for (int c = 0; c < 8; c++) acc[r][c] = 0.f;

    const int ti  = tid >> 5;       // 8 groups -> i0 = ti*8
    const int tc  = tid & 31;       // 32 groups -> c0 = tc*8
    const int ii0 = ti * 8;
    const int c0  = tc * 8;

    for (int jt = 0; jt < 64; jt++) {
        const int j0g = jt * 64;
        __syncthreads();   // previous AV reads of vt/Ss complete before reload

        // --- load k tile: k[b][o][j0g + j] -> ks[j][o] ---
        {
            int e  = tid * 2;
            int o  = e >> 4;
            int j4 = e & 15;
            const float* kp = &g_k[((size_t)b * CQ_ + o) * N_ + j0g + j4 * 4];
            float4 a = *(const float4*)kp;
            float4 c = *(const float4*)(kp + 4);
            ks[(j4 * 4 + 0) * QS_STRIDE + o] = a.x;
            ks[(j4 * 4 + 1) * QS_STRIDE + o] = a.y;
            ks[(j4 * 4 + 2) * QS_STRIDE + o] = a.z;
            ks[(j4 * 4 + 3) * QS_STRIDE + o] = a.w;
            ks[(j4 * 4 + 4) * QS_STRIDE + o] = c.x;
            ks[(j4 * 4 + 5) * QS_STRIDE + o] = c.y;
            ks[(j4 * 4 + 6) * QS_STRIDE + o] = c.z;
            ks[(j4 * 4 + 7) * QS_STRIDE + o] = c.w;
        }
        // --- load v tile: v[b][c][j0g + j] -> vt[j][c]  (256 x 64, transposed) ---
        {
            int j4 = tid & 15;
            int cb = tid >> 4;
#pragma unroll
            for (int r = 0; r < 16; r++) {
                int c = r * 16 + cb;
                float4 a = *(const float4*)&g_v[((size_t)b * C_ + c) * N_ + j0g + j4 * 4];
                vt[(j4 * 4 + 0) * VT_STRIDE + c] = a.x;
                vt[(j4 * 4 + 1) * VT_STRIDE + c] = a.y;
                vt[(j4 * 4 + 2) * VT_STRIDE + c] = a.z;
                vt[(j4 * 4 + 3) * VT_STRIDE + c] = a.w;
            }
        }
        __syncthreads();

        // --- S = q_tile (64x32) @ k_tile^T (32x64) -> Ss[i][j] ---
        {
            const int sj0 = (tid & 31) * 2;     // 2 j per thread
            const int si0 = (tid >> 5) * 8;     // 8 i per thread
            float s[8][2];
#pragma unroll
            for (int r = 0; r < 8; r++) { s[r][0] = 0.f; s[r][1] = 0.f; }
#pragma unroll
            for (int o = 0; o < 32; o++) {
                float k0 = ks[(sj0 + 0) * QS_STRIDE + o];
                float k1 = ks[(sj0 + 1) * QS_STRIDE + o];
#pragma unroll
                for (int r = 0; r < 8; r++) {
                    float qv = qs[(si0 + r) * QS_STRIDE + o];
                    s[r][0] += qv * k0;
                    s[r][1] += qv * k1;
                }
            }
#pragma unroll
            for (int r = 0; r < 8; r++) {
                Ss[(si0 + r) * SS_STRIDE + sj0 + 0] = s[r][0];
                Ss[(si0 + r) * SS_STRIDE + sj0 + 1] = s[r][1];
            }
        }
        __syncthreads();

        // --- online softmax: 4 lanes per row ---
        {
            const int i  = tid >> 2;
            const int qq = tid & 3;
            float* srow = &Ss[i * SS_STRIDE + qq * 16];
            float mx = -1e30f;
#pragma unroll
            for (int jj = 0; jj < 16; jj++) mx = fmaxf(mx, srow[jj]);
            mx = fmaxf(mx, __shfl_xor_sync(0xffffffffu, mx, 1));
            mx = fmaxf(mx, __shfl_xor_sync(0xffffffffu, mx, 2));
            float mo = m_[i];
            float mn = fmaxf(mo, mx);
            float cf = __expf(mo - mn);
            float sum = 0.f;
#pragma unroll
            for (int jj = 0; jj < 16; jj++) {
                float p = __expf(srow[jj] - mn);
                srow[jj] = p;
                sum += p;
            }
            sum += __shfl_xor_sync(0xffffffffu, sum, 1);
            sum += __shfl_xor_sync(0xffffffffu, sum, 2);
            if (qq == 0) {
                m_[i] = mn;
                cs[i] = cf;
                l_[i] = l_[i] * cf + sum;
            }
        }
        __syncthreads();

        // --- AV: acc[i][c] = acc*cf + P(64x64) @ vt(64x256) ---
        {
#pragma unroll
            for (int r = 0; r < 8; r++) {
                float f = cs[ii0 + r];
#pragma unroll
                for (int c = 0; c < 8; c++) acc[r][c] *= f;
            }
#pragma unroll 2
            for (int j = 0; j < 64; j++) {
                float4 v0 = *(float4*)&vt[j * VT_STRIDE + c0];
                float4 v1 = *(float4*)&vt[j * VT_STRIDE + c0 + 4];
                float vv[8] = {v0.x, v0.y, v0.z, v0.w, v1.x, v1.y, v1.z, v1.w};
                float p[8];
#pragma unroll
                for (int r = 0; r < 8; r++) p[r] = Ss[(ii0 + r) * SS_STRIDE + j];
#pragma unroll
                for (int r = 0; r < 8; r++)
#pragma unroll
                    for (int c = 0; c < 8; c++) acc[r][c] += p[r] * vv[c];
            }
        }
    }
    __syncthreads();

    // --- normalize + stage transposed: outs2[i][c] (reuse vt) ---
    float* outs2 = vt;
#pragma unroll
    for (int r = 0; r < 8; r++) {
        float inv = 1.0f / l_[ii0 + r];
#pragma unroll
        for (int c = 0; c < 8; c++)
            outs2[(ii0 + r) * O2_STRIDE + c0 + c] = acc[r][c] * inv;
    }
    __syncthreads();

    // --- epilogue: y[b][c][i] = gamma*out + x, coalesced along i ---
    {
        const float g   = gamma[0];
        const int w     = tid >> 5;
        const int lane  = tid & 31;
        for (int cl = w; cl < 256; cl += 8) {
            float o0 = outs2[(2 * lane + 0) * O2_STRIDE + cl];
            float o1 = outs2[(2 * lane + 1) * O2_STRIDE + cl];
            size_t gb = ((size_t)b * C_ + cl) * N_ + i0g + 2 * lane;
            float2 xv = *(const float2*)&x[gb];
            float2 yv = {g * o0 + xv.x, g * o1 + xv.y};
            *(float2*)&y[gb] = yv;
        }
    }
}

// ---------------------------------------------------------------------------
extern "C" void kernel_launch(void* const* d_in, const int* in_sizes, int n_in,
                              void* d_out, int out_size)
{
    const float* x     = (const float*)d_in[0];
    const float* wq    = (const float*)d_in[1];
    const float* bq    = (const float*)d_in[2];
    const float* wk    = (const float*)d_in[3];
    const float* bk    = (const float*)d_in[4];
    const float* wv    = (const float*)d_in[5];
    const float* bv    = (const float*)d_in[6];
    const float* gamma = (const float*)d_in[7];
    float* y = (float*)d_out;

    cudaFuncSetAttribute(attn_kernel,
                         cudaFuncAttributeMaxDynamicSharedMemorySize, SMEM_BYTES);

    proj_qk_kernel<<<dim3(N_ / 128, 2, B_), 256>>>(x, wq, bq, wk, bk);
    proj_v_kernel <<<dim3(N_ / 128, 2, B_), 256>>>(x, wv, bv);
    attn_kernel   <<<dim3(N_ / 64, B_), 256, SMEM_BYTES>>>(x, gamma, y);
}